// round 1
// baseline (speedup 1.0000x reference)
#include <cuda_runtime.h>
#include <cuda_bf16.h>
#include <math.h>

#define NMAX 50000
#define F 128
#define LN_EPS 1e-5f

// Scratch (device globals — no allocation allowed)
__device__ float g_XA[NMAX * F];      // x @ W1a + eb1
__device__ float g_XB[NMAX * F];      // x @ W1b
__device__ float g_AGGS[NMAX * F];    // segment_sum of silu(h)
__device__ float g_DELTA[NMAX * 3];   // segment_sum of scale*diff
__device__ float g_DEG[NMAX];         // degree (float)
__device__ float g_V[F];              // ew2 @ cw
__device__ float g_C0;                // eb2.cw + cb
__device__ int   g_IS64;              // edge_index dtype flag

// ---------------------------------------------------------------------------
// Detect whether edge_index buffer is int64 or int32.
// If int64 with values in [0,N), reading as int64 gives small in-range values.
// If int32, int64 reinterpretation packs two random ints -> huge values.
__global__ void detect_kernel(const void* ei, int E, int N) {
    if (blockIdx.x == 0 && threadIdx.x == 0) {
        const long long* p = (const long long*)ei;
        int cnt = (2 * E < 256) ? 2 * E : 256;
        int ok = 1;
        for (int i = 0; i < cnt; i++) {
            long long v = p[i];
            if (v < 0 || v >= N) { ok = 0; break; }
        }
        g_IS64 = ok;
    }
}

// ---------------------------------------------------------------------------
// Precompute V = ew2 @ cw (per-row dot), C0 = eb2.cw + cb
__global__ void prep_kernel(const float* __restrict__ ew2, const float* __restrict__ cw,
                            const float* __restrict__ eb2, const float* __restrict__ cb) {
    int t = threadIdx.x;
    float s = 0.f;
    for (int o = 0; o < F; o++) s += ew2[t * F + o] * cw[o];
    g_V[t] = s;
    if (t == 0) {
        float c = cb[0];
        for (int o = 0; o < F; o++) c += eb2[o] * cw[o];
        g_C0 = c;
    }
}

// ---------------------------------------------------------------------------
// Zero accumulators: AGGS (N*128), DELTA (N*3), DEG (N)
__global__ void zero_kernel(int N) {
    int total = N * 132;
    for (int i = blockIdx.x * blockDim.x + threadIdx.x; i < total;
         i += gridDim.x * blockDim.x) {
        if (i < N * 128)            g_AGGS[i] = 0.f;
        else if (i < N * 131)       g_DELTA[i - N * 128] = 0.f;
        else                        g_DEG[i - N * 131] = 0.f;
    }
}

// ---------------------------------------------------------------------------
// Generic skinny GEMM: out[N,128] = A[N,128] @ W[128,128] (+bias) (+deg*degvec) (silu?)
// Block: 128 threads, 16 rows per block.
template <int ACT>
__global__ void __launch_bounds__(128)
gemm128(const float* __restrict__ A, const float* __restrict__ W,
        const float* __restrict__ bias,
        const float* __restrict__ deg, const float* __restrict__ degvec,
        float* __restrict__ out, int N) {
    __shared__ float As[16][F];
    int row0 = blockIdx.x * 16;
    int tid = threadIdx.x;

#pragma unroll
    for (int r = 0; r < 16; r++) {
        int row = row0 + r;
        As[r][tid] = (row < N) ? A[(size_t)row * F + tid] : 0.f;
    }
    __syncthreads();

    float acc[16];
#pragma unroll
    for (int r = 0; r < 16; r++) acc[r] = 0.f;

#pragma unroll 4
    for (int k = 0; k < F; k++) {
        float wv = __ldg(&W[k * F + tid]);
#pragma unroll
        for (int r = 0; r < 16; r++) acc[r] += As[r][k] * wv;
    }

    float b = bias ? __ldg(&bias[tid]) : 0.f;
    float dv = degvec ? __ldg(&degvec[tid]) : 0.f;
#pragma unroll
    for (int r = 0; r < 16; r++) {
        int row = row0 + r;
        if (row < N) {
            float v = acc[r] + b;
            if (deg) v += deg[row] * dv;
            if (ACT == 1) v = v / (1.f + __expf(-v));  // silu
            out[(size_t)row * F + tid] = v;
        }
    }
}

// ---------------------------------------------------------------------------
// Edge kernel: one warp per edge.
// pre = XA[row] + XB[col] + dist2*w1c ; s = silu(pre)
// AGGS[row] += s ; DEG[row] += 1
// scale = tanh(s.V + C0) ; DELTA[row] += scale*diff
__global__ void __launch_bounds__(256)
edge_kernel(const void* __restrict__ ei_raw, const float* __restrict__ pos,
            const float* __restrict__ ew1, int E, int N) {
    int gw = (blockIdx.x * blockDim.x + threadIdx.x) >> 5;
    int lane = threadIdx.x & 31;
    if (gw >= E) return;

    int row, col;
    if (g_IS64) {
        const long long* ei = (const long long*)ei_raw;
        row = (int)ei[gw];
        col = (int)ei[(size_t)E + gw];
    } else {
        const int* ei = (const int*)ei_raw;
        row = ei[gw];
        col = ei[E + gw];
    }

    float dx = pos[row * 3 + 0] - pos[col * 3 + 0];
    float dy = pos[row * 3 + 1] - pos[col * 3 + 1];
    float dz = pos[row * 3 + 2] - pos[col * 3 + 2];
    float dist2 = dx * dx + dy * dy + dz * dz;

    const float4* XA4 = (const float4*)g_XA;
    const float4* XB4 = (const float4*)g_XB;
    float4 a = XA4[(size_t)row * 32 + lane];
    float4 b = XB4[(size_t)col * 32 + lane];
    float4 w = __ldg((const float4*)(ew1 + 256 * F) + lane);

    float p0 = a.x + b.x + dist2 * w.x;
    float p1 = a.y + b.y + dist2 * w.y;
    float p2 = a.z + b.z + dist2 * w.z;
    float p3 = a.w + b.w + dist2 * w.w;

    float s0 = p0 / (1.f + __expf(-p0));
    float s1 = p1 / (1.f + __expf(-p1));
    float s2 = p2 / (1.f + __expf(-p2));
    float s3 = p3 / (1.f + __expf(-p3));

    float* aggp = g_AGGS + (size_t)row * F + lane * 4;
    atomicAdd(aggp + 0, s0);
    atomicAdd(aggp + 1, s1);
    atomicAdd(aggp + 2, s2);
    atomicAdd(aggp + 3, s3);

    float4 vv = ((const float4*)g_V)[lane];
    float d = s0 * vv.x + s1 * vv.y + s2 * vv.z + s3 * vv.w;
#pragma unroll
    for (int o = 16; o > 0; o >>= 1) d += __shfl_xor_sync(0xffffffffu, d, o);

    if (lane == 0) {
        float sc = tanhf(d + g_C0);
        atomicAdd(&g_DELTA[row * 3 + 0], sc * dx);
        atomicAdd(&g_DELTA[row * 3 + 1], sc * dy);
        atomicAdd(&g_DELTA[row * 3 + 2], sc * dz);
        atomicAdd(&g_DEG[row], 1.0f);
    }
}

// ---------------------------------------------------------------------------
// Final node kernel: U = H @ nw2 + nb2 ; pre = x + U ; LayerNorm -> x_out
__global__ void __launch_bounds__(128)
node_final(const float* __restrict__ H, const float* __restrict__ nw2,
           const float* __restrict__ nb2, const float* __restrict__ x,
           const float* __restrict__ gamma, const float* __restrict__ beta,
           float* __restrict__ xout, int N) {
    __shared__ float As[16][F];
    __shared__ float P[16][F];
    __shared__ float s_mu[16], s_ri[16];

    int row0 = blockIdx.x * 16;
    int tid = threadIdx.x;

#pragma unroll
    for (int r = 0; r < 16; r++) {
        int row = row0 + r;
        As[r][tid] = (row < N) ? H[(size_t)row * F + tid] : 0.f;
    }
    __syncthreads();

    float acc[16];
#pragma unroll
    for (int r = 0; r < 16; r++) acc[r] = 0.f;
#pragma unroll 4
    for (int k = 0; k < F; k++) {
        float wv = __ldg(&nw2[k * F + tid]);
#pragma unroll
        for (int r = 0; r < 16; r++) acc[r] += As[r][k] * wv;
    }

    float b = __ldg(&nb2[tid]);
#pragma unroll
    for (int r = 0; r < 16; r++) {
        int row = row0 + r;
        float xv = (row < N) ? x[(size_t)row * F + tid] : 0.f;
        P[r][tid] = acc[r] + b + xv;
    }
    __syncthreads();

    // LayerNorm stats: 4 warps x 4 rows
    int w = tid >> 5, lane = tid & 31;
#pragma unroll
    for (int rr = 0; rr < 4; rr++) {
        int r = w * 4 + rr;
        float s = 0.f, s2 = 0.f;
#pragma unroll
        for (int t = 0; t < 4; t++) {
            float v = P[r][lane + t * 32];
            s += v;
            s2 += v * v;
        }
#pragma unroll
        for (int o = 16; o > 0; o >>= 1) {
            s  += __shfl_xor_sync(0xffffffffu, s, o);
            s2 += __shfl_xor_sync(0xffffffffu, s2, o);
        }
        if (lane == 0) {
            float mean = s * (1.f / F);
            float var = s2 * (1.f / F) - mean * mean;
            s_mu[r] = mean;
            s_ri[r] = rsqrtf(var + LN_EPS);
        }
    }
    __syncthreads();

    float g = __ldg(&gamma[tid]);
    float be = __ldg(&beta[tid]);
#pragma unroll
    for (int r = 0; r < 16; r++) {
        int row = row0 + r;
        if (row < N)
            xout[(size_t)row * F + tid] = g * (P[r][tid] - s_mu[r]) * s_ri[r] + be;
    }
}

// ---------------------------------------------------------------------------
// pos_out = pos + DELTA
__global__ void pos_kernel(const float* __restrict__ pos, float* __restrict__ out, int N) {
    int i = blockIdx.x * blockDim.x + threadIdx.x;
    if (i < N * 3) out[i] = pos[i] + g_DELTA[i];
}

// ---------------------------------------------------------------------------
extern "C" void kernel_launch(void* const* d_in, const int* in_sizes, int n_in,
                              void* d_out, int out_size) {
    const float* x     = (const float*)d_in[0];
    const float* pos   = (const float*)d_in[1];
    const void*  ei    = d_in[2];
    const float* ew1   = (const float*)d_in[3];
    const float* eb1   = (const float*)d_in[4];
    const float* ew2   = (const float*)d_in[5];
    const float* eb2   = (const float*)d_in[6];
    const float* nw1   = (const float*)d_in[7];
    const float* nb1   = (const float*)d_in[8];
    const float* nw2   = (const float*)d_in[9];
    const float* nb2   = (const float*)d_in[10];
    const float* cw    = (const float*)d_in[11];
    const float* cb    = (const float*)d_in[12];
    const float* gamma = (const float*)d_in[13];
    const float* beta  = (const float*)d_in[14];

    int N = in_sizes[0] / F;
    int E = in_sizes[2] / 2;

    float* xout = (float*)d_out;            // [N, 128]
    float* pout = (float*)d_out + (size_t)N * F;  // [N, 3]

    float* XA;   cudaGetSymbolAddress((void**)&XA,   g_XA);
    float* XB;   cudaGetSymbolAddress((void**)&XB,   g_XB);
    float* AGGS; cudaGetSymbolAddress((void**)&AGGS, g_AGGS);
    float* DEG;  cudaGetSymbolAddress((void**)&DEG,  g_DEG);

    int gblocks = (N + 15) / 16;

    detect_kernel<<<1, 32>>>(ei, E, N);
    prep_kernel<<<1, 128>>>(ew2, cw, eb2, cb);
    zero_kernel<<<4096, 256>>>(N);

    // XA = x @ W1a + eb1 ; XB = x @ W1b
    gemm128<0><<<gblocks, 128>>>(x, ew1,           eb1,  nullptr, nullptr, XA, N);
    gemm128<0><<<gblocks, 128>>>(x, ew1 + 128 * F, nullptr, nullptr, nullptr, XB, N);

    // Edge stage: scatter silu(h), degree, coordinate deltas
    int eblocks = (E * 32 + 255) / 256;
    edge_kernel<<<eblocks, 256>>>(ei, pos, ew1, E, N);

    // AGG = AGGS @ ew2 + deg * eb2   (into XA, reuse)
    gemm128<0><<<gblocks, 128>>>(AGGS, ew2, nullptr, DEG, eb2, XA, N);
    // H = silu(AGG @ nw1 + nb1)      (into XB, reuse)
    gemm128<1><<<gblocks, 128>>>(XA, nw1, nb1, nullptr, nullptr, XB, N);
    // x_out = LN(x + H @ nw2 + nb2)
    node_final<<<gblocks, 128>>>(XB, nw2, nb2, x, gamma, beta, xout, N);
    // pos_out = pos + delta
    pos_kernel<<<(N * 3 + 255) / 256, 256>>>(pos, pout, N);
}

// round 2
// speedup vs baseline: 1.3466x; 1.3466x over previous
#include <cuda_runtime.h>
#include <cuda_bf16.h>
#include <math.h>
#include <stdint.h>

#define NMAX 50000
#define F 128
#define LN_EPS 1e-5f

// Scratch (device globals — no allocation allowed)
__device__ float g_XA[NMAX * F];      // x @ W1a + eb1
__device__ float g_XB[NMAX * F];      // x @ W1b
__device__ float g_AGGS[NMAX * F];    // segment_sum of silu(h)
__device__ float g_DELTA[NMAX * 3];   // segment_sum of scale*diff
__device__ float g_DEG[NMAX];         // degree (float)
__device__ float g_V[F];              // ew2 @ cw
__device__ float g_C0;                // eb2.cw + cb
__device__ int   g_IS64;              // edge_index dtype flag

// ---------------------------------------------------------------------------
// Packed f32x2 helpers (sm_100+)
__device__ __forceinline__ unsigned long long pack2(float v) {
    unsigned long long r;
    unsigned int u = __float_as_uint(v);
    asm("mov.b64 %0, {%1, %1};" : "=l"(r) : "r"(u));
    return r;
}
#define FFMA2(acc, a, b) \
    asm("fma.rn.f32x2 %0, %1, %2, %0;" : "+l"(acc) : "l"(a), "l"(b))
#define LDS_2x64(v0, v1, addr) \
    asm("ld.shared.v2.b64 {%0, %1}, [%2];" : "=l"(v0), "=l"(v1) : "r"(addr))
__device__ __forceinline__ void unpack2(unsigned long long p, float& lo, float& hi) {
    unsigned int a, b;
    asm("mov.b64 {%0, %1}, %2;" : "=r"(a), "=r"(b) : "l"(p));
    lo = __uint_as_float(a);
    hi = __uint_as_float(b);
}

// ---------------------------------------------------------------------------
// Detect whether edge_index buffer is int64 or int32.
__global__ void detect_kernel(const void* ei, int E, int N) {
    if (blockIdx.x == 0 && threadIdx.x == 0) {
        const long long* p = (const long long*)ei;
        int cnt = (2 * E < 256) ? 2 * E : 256;
        int ok = 1;
        for (int i = 0; i < cnt; i++) {
            long long v = p[i];
            if (v < 0 || v >= N) { ok = 0; break; }
        }
        g_IS64 = ok;
    }
}

// ---------------------------------------------------------------------------
// Precompute V = ew2 @ cw (per-row dot), C0 = eb2.cw + cb
__global__ void prep_kernel(const float* __restrict__ ew2, const float* __restrict__ cw,
                            const float* __restrict__ eb2, const float* __restrict__ cb) {
    int t = threadIdx.x;
    float s = 0.f;
    for (int o = 0; o < F; o++) s += ew2[t * F + o] * cw[o];
    g_V[t] = s;
    if (t == 0) {
        float c = cb[0];
        for (int o = 0; o < F; o++) c += eb2[o] * cw[o];
        g_C0 = c;
    }
}

// ---------------------------------------------------------------------------
// Zero accumulators: AGGS (N*128) via float4, DELTA (N*3), DEG (N)
__global__ void zero_kernel(int N) {
    int n4 = N * 32;  // N*128/4
    float4 z4 = make_float4(0.f, 0.f, 0.f, 0.f);
    float4* a4 = (float4*)g_AGGS;
    int stride = gridDim.x * blockDim.x;
    for (int i = blockIdx.x * blockDim.x + threadIdx.x; i < n4; i += stride)
        a4[i] = z4;
    for (int i = blockIdx.x * blockDim.x + threadIdx.x; i < N * 3; i += stride)
        g_DELTA[i] = 0.f;
    for (int i = blockIdx.x * blockDim.x + threadIdx.x; i < N; i += stride)
        g_DEG[i] = 0.f;
}

// ---------------------------------------------------------------------------
// Skinny GEMM: out[N,128] = A[N,128] @ W[128,128] (+bias) (+deg*degvec) (silu?)
// Block: 128 threads, 16 rows. A staged transposed (k-major) in smem, stride 20
// floats (16B-aligned rows, 4-way write conflicts only). Inner loop uses
// LDS.128 + packed fma.rn.f32x2 (row pairs in b64 accumulators).
#define AS_STRIDE 20
template <int ACT>
__global__ void __launch_bounds__(128, 8)
gemm128(const float* __restrict__ A, const float* __restrict__ W,
        const float* __restrict__ bias,
        const float* __restrict__ deg, const float* __restrict__ degvec,
        float* __restrict__ out, int N) {
    __shared__ float As[F * AS_STRIDE];
    int tid = threadIdx.x;
    int row0 = blockIdx.x * 16;

    // Stage A transposed: As[k=tid][r] = A[row0+r][tid]
#pragma unroll
    for (int r = 0; r < 16; r++) {
        int row = row0 + r;
        As[tid * AS_STRIDE + r] = (row < N) ? A[(size_t)row * F + tid] : 0.f;
    }
    __syncthreads();

    uint32_t sb = (uint32_t)__cvta_generic_to_shared(As);
    unsigned long long acc[8];
#pragma unroll
    for (int j = 0; j < 8; j++) acc[j] = 0ull;

#pragma unroll 4
    for (int k = 0; k < F; k++) {
        float wv = __ldg(&W[k * F + tid]);
        unsigned long long wd = pack2(wv);
        uint32_t a = sb + k * (AS_STRIDE * 4);
        unsigned long long v0, v1, v2, v3, v4, v5, v6, v7;
        LDS_2x64(v0, v1, a);
        LDS_2x64(v2, v3, a + 16);
        LDS_2x64(v4, v5, a + 32);
        LDS_2x64(v6, v7, a + 48);
        FFMA2(acc[0], v0, wd);
        FFMA2(acc[1], v1, wd);
        FFMA2(acc[2], v2, wd);
        FFMA2(acc[3], v3, wd);
        FFMA2(acc[4], v4, wd);
        FFMA2(acc[5], v5, wd);
        FFMA2(acc[6], v6, wd);
        FFMA2(acc[7], v7, wd);
    }

    float b = bias ? __ldg(&bias[tid]) : 0.f;
    float dv = degvec ? __ldg(&degvec[tid]) : 0.f;
#pragma unroll
    for (int j = 0; j < 8; j++) {
        float lo, hi;
        unpack2(acc[j], lo, hi);
#pragma unroll
        for (int h = 0; h < 2; h++) {
            int row = row0 + 2 * j + h;
            if (row < N) {
                float v = (h ? hi : lo) + b;
                if (deg) v += deg[row] * dv;
                if (ACT == 1) v = v / (1.f + __expf(-v));  // silu
                out[(size_t)row * F + tid] = v;
            }
        }
    }
}

// ---------------------------------------------------------------------------
// Edge kernel: one warp per edge.
__global__ void __launch_bounds__(256)
edge_kernel(const void* __restrict__ ei_raw, const float* __restrict__ pos,
            const float* __restrict__ ew1, int E, int N) {
    int gw = (blockIdx.x * blockDim.x + threadIdx.x) >> 5;
    int lane = threadIdx.x & 31;
    if (gw >= E) return;

    int row, col;
    if (g_IS64) {
        const long long* ei = (const long long*)ei_raw;
        row = (int)ei[gw];
        col = (int)ei[(size_t)E + gw];
    } else {
        const int* ei = (const int*)ei_raw;
        row = ei[gw];
        col = ei[E + gw];
    }

    float dx = pos[row * 3 + 0] - pos[col * 3 + 0];
    float dy = pos[row * 3 + 1] - pos[col * 3 + 1];
    float dz = pos[row * 3 + 2] - pos[col * 3 + 2];
    float dist2 = dx * dx + dy * dy + dz * dz;

    const float4* XA4 = (const float4*)g_XA;
    const float4* XB4 = (const float4*)g_XB;
    float4 a = XA4[(size_t)row * 32 + lane];
    float4 b = XB4[(size_t)col * 32 + lane];
    float4 w = __ldg((const float4*)(ew1 + 256 * F) + lane);

    float p0 = a.x + b.x + dist2 * w.x;
    float p1 = a.y + b.y + dist2 * w.y;
    float p2 = a.z + b.z + dist2 * w.z;
    float p3 = a.w + b.w + dist2 * w.w;

    float s0 = p0 / (1.f + __expf(-p0));
    float s1 = p1 / (1.f + __expf(-p1));
    float s2 = p2 / (1.f + __expf(-p2));
    float s3 = p3 / (1.f + __expf(-p3));

    float* aggp = g_AGGS + (size_t)row * F + lane * 4;
    asm volatile("red.global.add.v4.f32 [%0], {%1, %2, %3, %4};"
                 :: "l"(aggp), "f"(s0), "f"(s1), "f"(s2), "f"(s3)
                 : "memory");

    float4 vv = ((const float4*)g_V)[lane];
    float d = s0 * vv.x + s1 * vv.y + s2 * vv.z + s3 * vv.w;
#pragma unroll
    for (int o = 16; o > 0; o >>= 1) d += __shfl_xor_sync(0xffffffffu, d, o);

    if (lane == 0) {
        float sc = tanhf(d + g_C0);
        atomicAdd(&g_DELTA[row * 3 + 0], sc * dx);
        atomicAdd(&g_DELTA[row * 3 + 1], sc * dy);
        atomicAdd(&g_DELTA[row * 3 + 2], sc * dz);
        atomicAdd(&g_DEG[row], 1.0f);
    }
}

// ---------------------------------------------------------------------------
// Final node kernel: U = H @ nw2 + nb2 ; pre = x + U ; LayerNorm -> x_out
__global__ void __launch_bounds__(128, 6)
node_final(const float* __restrict__ H, const float* __restrict__ nw2,
           const float* __restrict__ nb2, const float* __restrict__ x,
           const float* __restrict__ gamma, const float* __restrict__ beta,
           float* __restrict__ xout, int N) {
    __shared__ float As[F * AS_STRIDE];
    __shared__ float P[16][F];
    __shared__ float s_mu[16], s_ri[16];

    int tid = threadIdx.x;
    int row0 = blockIdx.x * 16;

#pragma unroll
    for (int r = 0; r < 16; r++) {
        int row = row0 + r;
        As[tid * AS_STRIDE + r] = (row < N) ? H[(size_t)row * F + tid] : 0.f;
    }
    __syncthreads();

    uint32_t sb = (uint32_t)__cvta_generic_to_shared(As);
    unsigned long long acc[8];
#pragma unroll
    for (int j = 0; j < 8; j++) acc[j] = 0ull;

#pragma unroll 4
    for (int k = 0; k < F; k++) {
        float wv = __ldg(&nw2[k * F + tid]);
        unsigned long long wd = pack2(wv);
        uint32_t a = sb + k * (AS_STRIDE * 4);
        unsigned long long v0, v1, v2, v3, v4, v5, v6, v7;
        LDS_2x64(v0, v1, a);
        LDS_2x64(v2, v3, a + 16);
        LDS_2x64(v4, v5, a + 32);
        LDS_2x64(v6, v7, a + 48);
        FFMA2(acc[0], v0, wd);
        FFMA2(acc[1], v1, wd);
        FFMA2(acc[2], v2, wd);
        FFMA2(acc[3], v3, wd);
        FFMA2(acc[4], v4, wd);
        FFMA2(acc[5], v5, wd);
        FFMA2(acc[6], v6, wd);
        FFMA2(acc[7], v7, wd);
    }

    float b = __ldg(&nb2[tid]);
#pragma unroll
    for (int j = 0; j < 8; j++) {
        float lo, hi;
        unpack2(acc[j], lo, hi);
#pragma unroll
        for (int h = 0; h < 2; h++) {
            int row = row0 + 2 * j + h;
            float xv = (row < N) ? x[(size_t)row * F + tid] : 0.f;
            P[2 * j + h][tid] = (h ? hi : lo) + b + xv;
        }
    }
    __syncthreads();

    // LayerNorm stats: 4 warps x 4 rows
    int w = tid >> 5, lane = tid & 31;
#pragma unroll
    for (int rr = 0; rr < 4; rr++) {
        int r = w * 4 + rr;
        float s = 0.f, s2 = 0.f;
#pragma unroll
        for (int t = 0; t < 4; t++) {
            float v = P[r][lane + t * 32];
            s += v;
            s2 += v * v;
        }
#pragma unroll
        for (int o = 16; o > 0; o >>= 1) {
            s  += __shfl_xor_sync(0xffffffffu, s, o);
            s2 += __shfl_xor_sync(0xffffffffu, s2, o);
        }
        if (lane == 0) {
            float mean = s * (1.f / F);
            float var = s2 * (1.f / F) - mean * mean;
            s_mu[r] = mean;
            s_ri[r] = rsqrtf(var + LN_EPS);
        }
    }
    __syncthreads();

    float g = __ldg(&gamma[tid]);
    float be = __ldg(&beta[tid]);
#pragma unroll
    for (int r = 0; r < 16; r++) {
        int row = row0 + r;
        if (row < N)
            xout[(size_t)row * F + tid] = g * (P[r][tid] - s_mu[r]) * s_ri[r] + be;
    }
}

// ---------------------------------------------------------------------------
// pos_out = pos + DELTA
__global__ void pos_kernel(const float* __restrict__ pos, float* __restrict__ out, int N) {
    int i = blockIdx.x * blockDim.x + threadIdx.x;
    if (i < N * 3) out[i] = pos[i] + g_DELTA[i];
}

// ---------------------------------------------------------------------------
extern "C" void kernel_launch(void* const* d_in, const int* in_sizes, int n_in,
                              void* d_out, int out_size) {
    const float* x     = (const float*)d_in[0];
    const float* pos   = (const float*)d_in[1];
    const void*  ei    = d_in[2];
    const float* ew1   = (const float*)d_in[3];
    const float* eb1   = (const float*)d_in[4];
    const float* ew2   = (const float*)d_in[5];
    const float* eb2   = (const float*)d_in[6];
    const float* nw1   = (const float*)d_in[7];
    const float* nb1   = (const float*)d_in[8];
    const float* nw2   = (const float*)d_in[9];
    const float* nb2   = (const float*)d_in[10];
    const float* cw    = (const float*)d_in[11];
    const float* cb    = (const float*)d_in[12];
    const float* gamma = (const float*)d_in[13];
    const float* beta  = (const float*)d_in[14];

    int N = in_sizes[0] / F;
    int E = in_sizes[2] / 2;

    float* xout = (float*)d_out;                  // [N, 128]
    float* pout = (float*)d_out + (size_t)N * F;  // [N, 3]

    float* XA;   cudaGetSymbolAddress((void**)&XA,   g_XA);
    float* XB;   cudaGetSymbolAddress((void**)&XB,   g_XB);
    float* AGGS; cudaGetSymbolAddress((void**)&AGGS, g_AGGS);
    float* DEG;  cudaGetSymbolAddress((void**)&DEG,  g_DEG);

    int gblocks = (N + 15) / 16;

    detect_kernel<<<1, 32>>>(ei, E, N);
    prep_kernel<<<1, 128>>>(ew2, cw, eb2, cb);
    zero_kernel<<<2048, 256>>>(N);

    // XA = x @ W1a + eb1 ; XB = x @ W1b
    gemm128<0><<<gblocks, 128>>>(x, ew1,           eb1,     nullptr, nullptr, XA, N);
    gemm128<0><<<gblocks, 128>>>(x, ew1 + 128 * F, nullptr, nullptr, nullptr, XB, N);

    // Edge stage: scatter silu(h), degree, coordinate deltas
    int eblocks = (E * 32 + 255) / 256;
    edge_kernel<<<eblocks, 256>>>(ei, pos, ew1, E, N);

    // AGG = AGGS @ ew2 + deg * eb2   (into XA, reuse)
    gemm128<0><<<gblocks, 128>>>(AGGS, ew2, nullptr, DEG, eb2, XA, N);
    // H = silu(AGG @ nw1 + nb1)      (into XB, reuse)
    gemm128<1><<<gblocks, 128>>>(XA, nw1, nb1, nullptr, nullptr, XB, N);
    // x_out = LN(x + H @ nw2 + nb2)
    node_final<<<gblocks, 128>>>(XB, nw2, nb2, x, gamma, beta, xout, N);
    // pos_out = pos + delta
    pos_kernel<<<(N * 3 + 255) / 256, 256>>>(pos, pout, N);
}

// round 4
// speedup vs baseline: 1.3652x; 1.0138x over previous
#include <cuda_runtime.h>
#include <cuda_bf16.h>
#include <math.h>
#include <stdint.h>

#define NMAX 50000
#define F 128
#define LN_EPS 1e-5f

// ---------------------------------------------------------------------------
// Scratch (device globals — no allocation allowed)
__device__ float g_XA[NMAX * F];      // x @ W1a + eb1
__device__ float g_XB[NMAX * F];      // x @ W1b
__device__ float g_AGGS[NMAX * F];    // segment_sum of silu(h); later P
__device__ float g_DELTA[NMAX * 3];
__device__ float g_DEG[NMAX];
__device__ float g_V[F];              // ew2 @ cw
__device__ float g_C0;                // eb2.cw + cb
__device__ int   g_IS64;

// ---------------------------------------------------------------------------
// Packed f32x2 helpers (proven to assemble on compute_103)
#define FFMA2(acc, a, b) \
    asm("fma.rn.f32x2 %0, %1, %2, %0;" : "+l"(acc) : "l"(a), "l"(b))
#define LDS_2x64(v0, v1, addr) \
    asm("ld.shared.v2.b64 {%0, %1}, [%2];" : "=l"(v0), "=l"(v1) : "r"(addr))
__device__ __forceinline__ void unpack2(unsigned long long p, float& lo, float& hi) {
    unsigned int a, b;
    asm("mov.b64 {%0, %1}, %2;" : "=r"(a), "=r"(b) : "l"(p));
    lo = __uint_as_float(a);
    hi = __uint_as_float(b);
}
__device__ __forceinline__ uint32_t smem_u32(const void* p) {
    uint32_t a;
    asm("{ .reg .u64 t; cvta.to.shared.u64 t, %1; cvt.u32.u64 %0, t; }"
        : "=r"(a) : "l"(p));
    return a;
}

// ---------------------------------------------------------------------------
__global__ void detect_kernel(const void* ei, int E, int N) {
    if (blockIdx.x == 0 && threadIdx.x == 0) {
        const long long* p = (const long long*)ei;
        int cnt = (2 * E < 256) ? 2 * E : 256;
        int ok = 1;
        for (int i = 0; i < cnt; i++) {
            long long v = p[i];
            if (v < 0 || v >= N) { ok = 0; break; }
        }
        g_IS64 = ok;
    }
}

__global__ void prep_vc(const float* __restrict__ ew2, const float* __restrict__ cw,
                        const float* __restrict__ eb2, const float* __restrict__ cb) {
    int t = threadIdx.x;
    float s = 0.f;
    for (int o = 0; o < F; o++) s += ew2[t * F + o] * cw[o];
    g_V[t] = s;
    if (t == 0) {
        float c = cb[0];
        for (int o = 0; o < F; o++) c += eb2[o] * cw[o];
        g_C0 = c;
    }
}

__global__ void zero_kernel(int N) {
    int n4 = N * 32;
    float4 z4 = make_float4(0.f, 0.f, 0.f, 0.f);
    float4* a4 = (float4*)g_AGGS;
    int stride = gridDim.x * blockDim.x;
    for (int i = blockIdx.x * blockDim.x + threadIdx.x; i < n4; i += stride) a4[i] = z4;
    for (int i = blockIdx.x * blockDim.x + threadIdx.x; i < N * 3; i += stride) g_DELTA[i] = 0.f;
    for (int i = blockIdx.x * blockDim.x + threadIdx.x; i < N; i += stride) g_DEG[i] = 0.f;
}

// ---------------------------------------------------------------------------
// Register-tiled GEMM: out[N,128] = A[N,128] @ W[128,128] (+bias)(+deg*degvec)(silu)
// 256 threads; each thread computes an 8x8 output tile via f32x2 FFMA.
// A tile staged DUPLICATED ((v,v) float2 pairs) so A fragments are ready-made
// broadcast f32x2 operands; W stays k-major (no transpose), B frags are natural
// column pairs. Inner loop: 6x LDS.128 + 32x FFMA2, zero packing movs.
//
// Smem: Ws [32][128] f32 at 0 (16KB); As2 [32][132] float2 at 16384 (33.8KB).
#define SM_WS 0
#define SM_AS 16384
#define AS_STRIDE2 132                   // float2 stride per k-row (1056 B)
#define SM_RT_TOTAL (16384 + 32 * AS_STRIDE2 * 8)   // 50176 B

template <int ACT>
__global__ void __launch_bounds__(256, 2)
gemm_rt(const float* __restrict__ A, const float* __restrict__ W,
        const float* __restrict__ bias, const float* __restrict__ deg,
        const float* __restrict__ degvec, float* __restrict__ out, int N) {
    extern __shared__ char smem[];
    float*  Ws  = (float*)(smem + SM_WS);
    float2* As2 = (float2*)(smem + SM_AS);

    int t = threadIdx.x;
    int tx = t & 15, ty = t >> 4;
    int row0 = blockIdx.x * 128;

    unsigned long long acc[8][4];
#pragma unroll
    for (int r = 0; r < 8; r++)
#pragma unroll
        for (int c = 0; c < 4; c++) acc[r][c] = 0ull;

    uint32_t sb = smem_u32(smem);
    uint32_t aBase = sb + SM_AS + (uint32_t)ty * 64;   // ty*8 rows dup = 64 B
    uint32_t bBase = sb + SM_WS + (uint32_t)tx * 32;   // tx*8 floats = 32 B

    int ar = t >> 1;                 // A staging row 0..127
    int kh = (t & 1) * 16;           // k half within 32-chunk
    int arow = row0 + ar;

#pragma unroll 1
    for (int c = 0; c < 4; c++) {
        int k0 = c * 32;
        __syncthreads();
        // Stage W chunk: direct k-major copy (coalesced float4)
        {
            int k = t >> 3, col = (t & 7) * 16;
            const float4* src = (const float4*)(W + (size_t)(k0 + k) * F + col);
            float4* dst = (float4*)(Ws + k * F + col);
            dst[0] = __ldg(&src[0]);
            dst[1] = __ldg(&src[1]);
            dst[2] = __ldg(&src[2]);
            dst[3] = __ldg(&src[3]);
        }
        // Stage A chunk, transposed + duplicated
        {
            float4 v[4];
            if (arow < N) {
                const float4* src = (const float4*)(A + (size_t)arow * F + k0 + kh);
                v[0] = __ldg(&src[0]);
                v[1] = __ldg(&src[1]);
                v[2] = __ldg(&src[2]);
                v[3] = __ldg(&src[3]);
            } else {
#pragma unroll
                for (int q = 0; q < 4; q++) v[q] = make_float4(0.f, 0.f, 0.f, 0.f);
            }
#pragma unroll
            for (int q = 0; q < 4; q++) {
                float vals[4] = {v[q].x, v[q].y, v[q].z, v[q].w};
#pragma unroll
                for (int e = 0; e < 4; e++) {
                    int kk = kh + q * 4 + e;
                    As2[kk * AS_STRIDE2 + ar] = make_float2(vals[e], vals[e]);
                }
            }
        }
        __syncthreads();

#pragma unroll
        for (int kk = 0; kk < 32; kk++) {
            uint32_t aa = aBase + (uint32_t)kk * (AS_STRIDE2 * 8);
            uint32_t bb = bBase + (uint32_t)kk * (F * 4);
            unsigned long long a0, a1, a2, a3, a4, a5, a6, a7;
            unsigned long long b0, b1, b2, b3;
            LDS_2x64(a0, a1, aa);
            LDS_2x64(a2, a3, aa + 16);
            LDS_2x64(a4, a5, aa + 32);
            LDS_2x64(a6, a7, aa + 48);
            LDS_2x64(b0, b1, bb);
            LDS_2x64(b2, b3, bb + 16);
            FFMA2(acc[0][0], a0, b0); FFMA2(acc[0][1], a0, b1);
            FFMA2(acc[0][2], a0, b2); FFMA2(acc[0][3], a0, b3);
            FFMA2(acc[1][0], a1, b0); FFMA2(acc[1][1], a1, b1);
            FFMA2(acc[1][2], a1, b2); FFMA2(acc[1][3], a1, b3);
            FFMA2(acc[2][0], a2, b0); FFMA2(acc[2][1], a2, b1);
            FFMA2(acc[2][2], a2, b2); FFMA2(acc[2][3], a2, b3);
            FFMA2(acc[3][0], a3, b0); FFMA2(acc[3][1], a3, b1);
            FFMA2(acc[3][2], a3, b2); FFMA2(acc[3][3], a3, b3);
            FFMA2(acc[4][0], a4, b0); FFMA2(acc[4][1], a4, b1);
            FFMA2(acc[4][2], a4, b2); FFMA2(acc[4][3], a4, b3);
            FFMA2(acc[5][0], a5, b0); FFMA2(acc[5][1], a5, b1);
            FFMA2(acc[5][2], a5, b2); FFMA2(acc[5][3], a5, b3);
            FFMA2(acc[6][0], a6, b0); FFMA2(acc[6][1], a6, b1);
            FFMA2(acc[6][2], a6, b2); FFMA2(acc[6][3], a6, b3);
            FFMA2(acc[7][0], a7, b0); FFMA2(acc[7][1], a7, b1);
            FFMA2(acc[7][2], a7, b2); FFMA2(acc[7][3], a7, b3);
        }
    }

    // Epilogue
    float bcol[8], dcol[8];
#pragma unroll
    for (int j = 0; j < 8; j++) {
        bcol[j] = bias ? __ldg(&bias[tx * 8 + j]) : 0.f;
        dcol[j] = degvec ? __ldg(&degvec[tx * 8 + j]) : 0.f;
    }
#pragma unroll
    for (int rr = 0; rr < 8; rr++) {
        int row = row0 + ty * 8 + rr;
        if (row < N) {
            float dg = deg ? deg[row] : 0.f;
            float o[8];
#pragma unroll
            for (int cp = 0; cp < 4; cp++) unpack2(acc[rr][cp], o[2 * cp], o[2 * cp + 1]);
#pragma unroll
            for (int j = 0; j < 8; j++) {
                float v = o[j] + bcol[j] + dg * dcol[j];
                if (ACT == 1) v = v / (1.f + __expf(-v));
                o[j] = v;
            }
            float4* op = (float4*)(out + (size_t)row * F + tx * 8);
            op[0] = make_float4(o[0], o[1], o[2], o[3]);
            op[1] = make_float4(o[4], o[5], o[6], o[7]);
        }
    }
}

// ---------------------------------------------------------------------------
// Edge kernel: one warp per edge.
__global__ void __launch_bounds__(256)
edge_kernel(const void* __restrict__ ei_raw, const float* __restrict__ pos,
            const float* __restrict__ ew1, int E, int N) {
    int gw = (blockIdx.x * blockDim.x + threadIdx.x) >> 5;
    int lane = threadIdx.x & 31;
    if (gw >= E) return;

    int row, col;
    if (g_IS64) {
        const long long* ei = (const long long*)ei_raw;
        row = (int)ei[gw];
        col = (int)ei[(size_t)E + gw];
    } else {
        const int* ei = (const int*)ei_raw;
        row = ei[gw];
        col = ei[E + gw];
    }

    float dx = pos[row * 3 + 0] - pos[col * 3 + 0];
    float dy = pos[row * 3 + 1] - pos[col * 3 + 1];
    float dz = pos[row * 3 + 2] - pos[col * 3 + 2];
    float dist2 = dx * dx + dy * dy + dz * dz;

    const float4* XA4 = (const float4*)g_XA;
    const float4* XB4 = (const float4*)g_XB;
    float4 a = XA4[(size_t)row * 32 + lane];
    float4 b = XB4[(size_t)col * 32 + lane];
    float4 w = __ldg((const float4*)(ew1 + 256 * F) + lane);

    float p0 = a.x + b.x + dist2 * w.x;
    float p1 = a.y + b.y + dist2 * w.y;
    float p2 = a.z + b.z + dist2 * w.z;
    float p3 = a.w + b.w + dist2 * w.w;

    float s0 = p0 / (1.f + __expf(-p0));
    float s1 = p1 / (1.f + __expf(-p1));
    float s2 = p2 / (1.f + __expf(-p2));
    float s3 = p3 / (1.f + __expf(-p3));

    float* aggp = g_AGGS + (size_t)row * F + lane * 4;
    asm volatile("red.global.add.v4.f32 [%0], {%1, %2, %3, %4};"
                 :: "l"(aggp), "f"(s0), "f"(s1), "f"(s2), "f"(s3) : "memory");

    float4 vv = ((const float4*)g_V)[lane];
    float d = s0 * vv.x + s1 * vv.y + s2 * vv.z + s3 * vv.w;
#pragma unroll
    for (int o = 16; o > 0; o >>= 1) d += __shfl_xor_sync(0xffffffffu, d, o);

    if (lane == 0) {
        float sc = tanhf(d + g_C0);
        atomicAdd(&g_DELTA[row * 3 + 0], sc * dx);
        atomicAdd(&g_DELTA[row * 3 + 1], sc * dy);
        atomicAdd(&g_DELTA[row * 3 + 2], sc * dz);
        atomicAdd(&g_DEG[row], 1.0f);
    }
}

// ---------------------------------------------------------------------------
// Residual + LayerNorm: xout = LN(P + x)
__global__ void __launch_bounds__(256)
ln_kernel(const float* __restrict__ P, const float* __restrict__ x,
          const float* __restrict__ gamma, const float* __restrict__ beta,
          float* __restrict__ xout, int N) {
    int row = blockIdx.x * 8 + (threadIdx.x >> 5);
    int lane = threadIdx.x & 31;
    if (row >= N) return;
    float4 p = ((const float4*)P)[(size_t)row * 32 + lane];
    float4 xv = ((const float4*)x)[(size_t)row * 32 + lane];
    float4 pre = make_float4(p.x + xv.x, p.y + xv.y, p.z + xv.z, p.w + xv.w);
    float s = pre.x + pre.y + pre.z + pre.w;
    float s2 = pre.x * pre.x + pre.y * pre.y + pre.z * pre.z + pre.w * pre.w;
#pragma unroll
    for (int o = 16; o > 0; o >>= 1) {
        s  += __shfl_xor_sync(0xffffffffu, s, o);
        s2 += __shfl_xor_sync(0xffffffffu, s2, o);
    }
    float mean = s * (1.f / F);
    float ri = rsqrtf(s2 * (1.f / F) - mean * mean + LN_EPS);
    float4 g = ((const float4*)gamma)[lane];
    float4 b = ((const float4*)beta)[lane];
    float4 o;
    o.x = g.x * (pre.x - mean) * ri + b.x;
    o.y = g.y * (pre.y - mean) * ri + b.y;
    o.z = g.z * (pre.z - mean) * ri + b.z;
    o.w = g.w * (pre.w - mean) * ri + b.w;
    ((float4*)xout)[(size_t)row * 32 + lane] = o;
}

__global__ void pos_kernel(const float* __restrict__ pos, float* __restrict__ out, int N) {
    int i = blockIdx.x * blockDim.x + threadIdx.x;
    if (i < N * 3) out[i] = pos[i] + g_DELTA[i];
}

// ---------------------------------------------------------------------------
extern "C" void kernel_launch(void* const* d_in, const int* in_sizes, int n_in,
                              void* d_out, int out_size) {
    const float* x     = (const float*)d_in[0];
    const float* pos   = (const float*)d_in[1];
    const void*  ei    = d_in[2];
    const float* ew1   = (const float*)d_in[3];
    const float* eb1   = (const float*)d_in[4];
    const float* ew2   = (const float*)d_in[5];
    const float* eb2   = (const float*)d_in[6];
    const float* nw1   = (const float*)d_in[7];
    const float* nb1   = (const float*)d_in[8];
    const float* nw2   = (const float*)d_in[9];
    const float* nb2   = (const float*)d_in[10];
    const float* cw    = (const float*)d_in[11];
    const float* cb    = (const float*)d_in[12];
    const float* gamma = (const float*)d_in[13];
    const float* beta  = (const float*)d_in[14];

    int N = in_sizes[0] / F;
    int E = in_sizes[2] / 2;

    float* xout = (float*)d_out;
    float* pout = (float*)d_out + (size_t)N * F;

    float* XA;   cudaGetSymbolAddress((void**)&XA,   g_XA);
    float* XB;   cudaGetSymbolAddress((void**)&XB,   g_XB);
    float* AGGS; cudaGetSymbolAddress((void**)&AGGS, g_AGGS);
    float* DEG;  cudaGetSymbolAddress((void**)&DEG,  g_DEG);

    static int smem_set = 0;
    if (!smem_set) {
        cudaFuncSetAttribute(gemm_rt<0>, cudaFuncAttributeMaxDynamicSharedMemorySize, SM_RT_TOTAL);
        cudaFuncSetAttribute(gemm_rt<1>, cudaFuncAttributeMaxDynamicSharedMemorySize, SM_RT_TOTAL);
        smem_set = 1;
    }

    int tcb = (N + 127) / 128;

    detect_kernel<<<1, 32>>>(ei, E, N);
    prep_vc<<<1, 128>>>(ew2, cw, eb2, cb);
    zero_kernel<<<2048, 256>>>(N);

    // XA = x @ W1a + eb1 ; XB = x @ W1b
    gemm_rt<0><<<tcb, 256, SM_RT_TOTAL>>>(x, ew1,           eb1,     nullptr, nullptr, XA, N);
    gemm_rt<0><<<tcb, 256, SM_RT_TOTAL>>>(x, ew1 + 128 * F, nullptr, nullptr, nullptr, XB, N);

    // Edge stage
    int eblocks = (E * 32 + 255) / 256;
    edge_kernel<<<eblocks, 256>>>(ei, pos, ew1, E, N);

    // AGG = AGGS @ ew2 + deg*eb2  -> XA
    gemm_rt<0><<<tcb, 256, SM_RT_TOTAL>>>(AGGS, ew2, nullptr, DEG, eb2, XA, N);
    // H = silu(AGG @ nw1 + nb1)   -> XB
    gemm_rt<1><<<tcb, 256, SM_RT_TOTAL>>>(XA, nw1, nb1, nullptr, nullptr, XB, N);
    // P = H @ nw2 + nb2           -> AGGS (reuse)
    gemm_rt<0><<<tcb, 256, SM_RT_TOTAL>>>(XB, nw2, nb2, nullptr, nullptr, AGGS, N);
    // x_out = LN(x + P)
    ln_kernel<<<(N + 7) / 8, 256>>>(AGGS, x, gamma, beta, xout, N);
    // pos_out
    pos_kernel<<<(N * 3 + 255) / 256, 256>>>(pos, pout, N);
}

// round 5
// speedup vs baseline: 1.6016x; 1.1731x over previous
#include <cuda_runtime.h>
#include <cuda_bf16.h>
#include <math.h>
#include <stdint.h>

#define NMAX 50000
#define F 128
#define LN_EPS 1e-5f

// ---------------------------------------------------------------------------
// Scratch (device globals — no allocation allowed)
__device__ float g_XA[NMAX * F];
__device__ float g_XB[NMAX * F];
__device__ float g_AGGS[NMAX * F];
__device__ float g_DELTA[NMAX * 3];
__device__ float g_DEG[NMAX];
__device__ float g_V[F];
__device__ float g_C0;
__device__ int   g_IS64;

// ---------------------------------------------------------------------------
#define FFMA2(acc, a, b) \
    asm("fma.rn.f32x2 %0, %1, %2, %0;" : "+l"(acc) : "l"(a), "l"(b))
__device__ __forceinline__ unsigned long long pack2(float v) {
    unsigned long long r;
    unsigned int u = __float_as_uint(v);
    asm("mov.b64 %0, {%1, %1};" : "=l"(r) : "r"(u));
    return r;
}
__device__ __forceinline__ void unpack2(unsigned long long p, float& lo, float& hi) {
    unsigned int a, b;
    asm("mov.b64 {%0, %1}, %2;" : "=r"(a), "=r"(b) : "l"(p));
    lo = __uint_as_float(a);
    hi = __uint_as_float(b);
}

// ---------------------------------------------------------------------------
__global__ void detect_kernel(const void* ei, int E, int N) {
    if (blockIdx.x == 0 && threadIdx.x == 0) {
        const long long* p = (const long long*)ei;
        int cnt = (2 * E < 256) ? 2 * E : 256;
        int ok = 1;
        for (int i = 0; i < cnt; i++) {
            long long v = p[i];
            if (v < 0 || v >= N) { ok = 0; break; }
        }
        g_IS64 = ok;
    }
}

__global__ void prep_vc(const float* __restrict__ ew2, const float* __restrict__ cw,
                        const float* __restrict__ eb2, const float* __restrict__ cb) {
    int t = threadIdx.x;
    float s = 0.f;
    for (int o = 0; o < F; o++) s += ew2[t * F + o] * cw[o];
    g_V[t] = s;
    if (t == 0) {
        float c = cb[0];
        for (int o = 0; o < F; o++) c += eb2[o] * cw[o];
        g_C0 = c;
    }
}

__global__ void zero_kernel(int N) {
    int n4 = N * 32;
    float4 z4 = make_float4(0.f, 0.f, 0.f, 0.f);
    float4* a4 = (float4*)g_AGGS;
    int stride = gridDim.x * blockDim.x;
    for (int i = blockIdx.x * blockDim.x + threadIdx.x; i < n4; i += stride) a4[i] = z4;
    for (int i = blockIdx.x * blockDim.x + threadIdx.x; i < N * 3; i += stride) g_DELTA[i] = 0.f;
    for (int i = blockIdx.x * blockDim.x + threadIdx.x; i < N; i += stride) g_DEG[i] = 0.f;
}

// ---------------------------------------------------------------------------
// Register-tiled GEMM, conflict-free warp geometry.
// 256 threads; warp = 4 tx * 8 ty; block = (4 wx * 4 tx)*8 = 128 cols,
// (2 wy * 8 ty)*8 = 128 rows. Each thread: 8x8 tile via f32x2.
// A staged plain (k-major, stride 132 floats), loaded as 2x LDS.128 per k and
// duplicated in registers (ALU movs). B (weights) k-major, natural col pairs,
// single-phase broadcast LDS.128.
// Dual-output mode: gridDim.y==2 selects (W1,bias1,out1) for blockIdx.y==1.
#define SM_WS 0
#define SM_AS 16384
#define AS_STRIDE 132
#define SM_RT_TOTAL (16384 + 32 * AS_STRIDE * 4)   // 33280 B

template <int ACT>
__global__ void __launch_bounds__(256, 2)
gemm_rt(const float* __restrict__ A,
        const float* __restrict__ W0, const float* __restrict__ bias0,
        float* __restrict__ out0,
        const float* __restrict__ W1, const float* __restrict__ bias1,
        float* __restrict__ out1,
        const float* __restrict__ deg, const float* __restrict__ degvec, int N) {
    extern __shared__ char smem[];
    float* Ws = (float*)(smem + SM_WS);
    float* As = (float*)(smem + SM_AS);

    const float* W = W0;
    const float* bias = bias0;
    float* out = out0;
    if (blockIdx.y == 1) { W = W1; bias = bias1; out = out1; }

    int t = threadIdx.x;
    int lane = t & 31, w = t >> 5;
    int txl = lane & 3, tyl = lane >> 2;
    int wx = w & 3, wy = w >> 2;
    int col0 = (wx * 4 + txl) * 8;
    int rowt = (wy * 8 + tyl) * 8;
    int row0 = blockIdx.x * 128;

    unsigned long long acc[8][4];
#pragma unroll
    for (int r = 0; r < 8; r++)
#pragma unroll
        for (int c = 0; c < 4; c++) acc[r][c] = 0ull;

    int ar = t >> 1;              // A staging row 0..127
    int kh = (t & 1) * 16;        // k half within 32-chunk
    int arow = row0 + ar;

#pragma unroll 1
    for (int c = 0; c < 4; c++) {
        int k0 = c * 32;
        __syncthreads();
        // Stage W chunk (k-major, coalesced)
        {
            int k = t >> 3, col = (t & 7) * 16;
            const float4* src = (const float4*)(W + (size_t)(k0 + k) * F + col);
            float4* dst = (float4*)(Ws + k * F + col);
            dst[0] = __ldg(&src[0]);
            dst[1] = __ldg(&src[1]);
            dst[2] = __ldg(&src[2]);
            dst[3] = __ldg(&src[3]);
        }
        // Stage A chunk transposed (plain floats)
        {
            float4 v[4];
            if (arow < N) {
                const float4* src = (const float4*)(A + (size_t)arow * F + k0 + kh);
                v[0] = __ldg(&src[0]);
                v[1] = __ldg(&src[1]);
                v[2] = __ldg(&src[2]);
                v[3] = __ldg(&src[3]);
            } else {
#pragma unroll
                for (int q = 0; q < 4; q++) v[q] = make_float4(0.f, 0.f, 0.f, 0.f);
            }
#pragma unroll
            for (int q = 0; q < 4; q++) {
                float vals[4] = {v[q].x, v[q].y, v[q].z, v[q].w};
#pragma unroll
                for (int e = 0; e < 4; e++)
                    As[(kh + q * 4 + e) * AS_STRIDE + ar] = vals[e];
            }
        }
        __syncthreads();

#pragma unroll
        for (int kk = 0; kk < 32; kk++) {
            float4 al = *(const float4*)&As[kk * AS_STRIDE + rowt];
            float4 ah = *(const float4*)&As[kk * AS_STRIDE + rowt + 4];
            unsigned long long a0 = pack2(al.x), a1 = pack2(al.y);
            unsigned long long a2 = pack2(al.z), a3 = pack2(al.w);
            unsigned long long a4 = pack2(ah.x), a5 = pack2(ah.y);
            unsigned long long a6 = pack2(ah.z), a7 = pack2(ah.w);
            ulonglong2 bv0 = *(const ulonglong2*)&Ws[kk * F + col0];
            ulonglong2 bv1 = *(const ulonglong2*)&Ws[kk * F + col0 + 4];
            FFMA2(acc[0][0], a0, bv0.x); FFMA2(acc[0][1], a0, bv0.y);
            FFMA2(acc[0][2], a0, bv1.x); FFMA2(acc[0][3], a0, bv1.y);
            FFMA2(acc[1][0], a1, bv0.x); FFMA2(acc[1][1], a1, bv0.y);
            FFMA2(acc[1][2], a1, bv1.x); FFMA2(acc[1][3], a1, bv1.y);
            FFMA2(acc[2][0], a2, bv0.x); FFMA2(acc[2][1], a2, bv0.y);
            FFMA2(acc[2][2], a2, bv1.x); FFMA2(acc[2][3], a2, bv1.y);
            FFMA2(acc[3][0], a3, bv0.x); FFMA2(acc[3][1], a3, bv0.y);
            FFMA2(acc[3][2], a3, bv1.x); FFMA2(acc[3][3], a3, bv1.y);
            FFMA2(acc[4][0], a4, bv0.x); FFMA2(acc[4][1], a4, bv0.y);
            FFMA2(acc[4][2], a4, bv1.x); FFMA2(acc[4][3], a4, bv1.y);
            FFMA2(acc[5][0], a5, bv0.x); FFMA2(acc[5][1], a5, bv0.y);
            FFMA2(acc[5][2], a5, bv1.x); FFMA2(acc[5][3], a5, bv1.y);
            FFMA2(acc[6][0], a6, bv0.x); FFMA2(acc[6][1], a6, bv0.y);
            FFMA2(acc[6][2], a6, bv1.x); FFMA2(acc[6][3], a6, bv1.y);
            FFMA2(acc[7][0], a7, bv0.x); FFMA2(acc[7][1], a7, bv0.y);
            FFMA2(acc[7][2], a7, bv1.x); FFMA2(acc[7][3], a7, bv1.y);
        }
    }

    // Epilogue
    float bcol[8], dcol[8];
#pragma unroll
    for (int j = 0; j < 8; j++) {
        bcol[j] = bias ? __ldg(&bias[col0 + j]) : 0.f;
        dcol[j] = degvec ? __ldg(&degvec[col0 + j]) : 0.f;
    }
#pragma unroll
    for (int rr = 0; rr < 8; rr++) {
        int row = row0 + rowt + rr;
        if (row < N) {
            float dg = deg ? deg[row] : 0.f;
            float o[8];
#pragma unroll
            for (int cp = 0; cp < 4; cp++) unpack2(acc[rr][cp], o[2 * cp], o[2 * cp + 1]);
#pragma unroll
            for (int j = 0; j < 8; j++) {
                float v = o[j] + bcol[j] + dg * dcol[j];
                if (ACT == 1) v = v / (1.f + __expf(-v));
                o[j] = v;
            }
            float4* op = (float4*)(out + (size_t)row * F + col0);
            op[0] = make_float4(o[0], o[1], o[2], o[3]);
            op[1] = make_float4(o[4], o[5], o[6], o[7]);
        }
    }
}

// ---------------------------------------------------------------------------
// Edge kernel: one warp per edge.
__global__ void __launch_bounds__(256)
edge_kernel(const void* __restrict__ ei_raw, const float* __restrict__ pos,
            const float* __restrict__ ew1, int E, int N) {
    int gw = (blockIdx.x * blockDim.x + threadIdx.x) >> 5;
    int lane = threadIdx.x & 31;
    if (gw >= E) return;

    int row, col;
    if (g_IS64) {
        const long long* ei = (const long long*)ei_raw;
        row = (int)ei[gw];
        col = (int)ei[(size_t)E + gw];
    } else {
        const int* ei = (const int*)ei_raw;
        row = ei[gw];
        col = ei[E + gw];
    }

    float dx = pos[row * 3 + 0] - pos[col * 3 + 0];
    float dy = pos[row * 3 + 1] - pos[col * 3 + 1];
    float dz = pos[row * 3 + 2] - pos[col * 3 + 2];
    float dist2 = dx * dx + dy * dy + dz * dz;

    const float4* XA4 = (const float4*)g_XA;
    const float4* XB4 = (const float4*)g_XB;
    float4 a = XA4[(size_t)row * 32 + lane];
    float4 b = XB4[(size_t)col * 32 + lane];
    float4 w = __ldg((const float4*)(ew1 + 256 * F) + lane);

    float p0 = a.x + b.x + dist2 * w.x;
    float p1 = a.y + b.y + dist2 * w.y;
    float p2 = a.z + b.z + dist2 * w.z;
    float p3 = a.w + b.w + dist2 * w.w;

    float s0 = p0 / (1.f + __expf(-p0));
    float s1 = p1 / (1.f + __expf(-p1));
    float s2 = p2 / (1.f + __expf(-p2));
    float s3 = p3 / (1.f + __expf(-p3));

    float* aggp = g_AGGS + (size_t)row * F + lane * 4;
    asm volatile("red.global.add.v4.f32 [%0], {%1, %2, %3, %4};"
                 :: "l"(aggp), "f"(s0), "f"(s1), "f"(s2), "f"(s3) : "memory");

    float4 vv = ((const float4*)g_V)[lane];
    float d = s0 * vv.x + s1 * vv.y + s2 * vv.z + s3 * vv.w;
#pragma unroll
    for (int o = 16; o > 0; o >>= 1) d += __shfl_xor_sync(0xffffffffu, d, o);

    if (lane == 0) {
        float sc = tanhf(d + g_C0);
        atomicAdd(&g_DELTA[row * 3 + 0], sc * dx);
        atomicAdd(&g_DELTA[row * 3 + 1], sc * dy);
        atomicAdd(&g_DELTA[row * 3 + 2], sc * dz);
        atomicAdd(&g_DEG[row], 1.0f);
    }
}

// ---------------------------------------------------------------------------
// Residual + LayerNorm: xout = LN(P + x)
__global__ void __launch_bounds__(256)
ln_kernel(const float* __restrict__ P, const float* __restrict__ x,
          const float* __restrict__ gamma, const float* __restrict__ beta,
          float* __restrict__ xout, int N) {
    int row = blockIdx.x * 8 + (threadIdx.x >> 5);
    int lane = threadIdx.x & 31;
    if (row >= N) return;
    float4 p = ((const float4*)P)[(size_t)row * 32 + lane];
    float4 xv = ((const float4*)x)[(size_t)row * 32 + lane];
    float4 pre = make_float4(p.x + xv.x, p.y + xv.y, p.z + xv.z, p.w + xv.w);
    float s = pre.x + pre.y + pre.z + pre.w;
    float s2 = pre.x * pre.x + pre.y * pre.y + pre.z * pre.z + pre.w * pre.w;
#pragma unroll
    for (int o = 16; o > 0; o >>= 1) {
        s  += __shfl_xor_sync(0xffffffffu, s, o);
        s2 += __shfl_xor_sync(0xffffffffu, s2, o);
    }
    float mean = s * (1.f / F);
    float ri = rsqrtf(s2 * (1.f / F) - mean * mean + LN_EPS);
    float4 g = ((const float4*)gamma)[lane];
    float4 b = ((const float4*)beta)[lane];
    float4 o;
    o.x = g.x * (pre.x - mean) * ri + b.x;
    o.y = g.y * (pre.y - mean) * ri + b.y;
    o.z = g.z * (pre.z - mean) * ri + b.z;
    o.w = g.w * (pre.w - mean) * ri + b.w;
    ((float4*)xout)[(size_t)row * 32 + lane] = o;
}

__global__ void pos_kernel(const float* __restrict__ pos, float* __restrict__ out, int N) {
    int i = blockIdx.x * blockDim.x + threadIdx.x;
    if (i < N * 3) out[i] = pos[i] + g_DELTA[i];
}

// ---------------------------------------------------------------------------
extern "C" void kernel_launch(void* const* d_in, const int* in_sizes, int n_in,
                              void* d_out, int out_size) {
    const float* x     = (const float*)d_in[0];
    const float* pos   = (const float*)d_in[1];
    const void*  ei    = d_in[2];
    const float* ew1   = (const float*)d_in[3];
    const float* eb1   = (const float*)d_in[4];
    const float* ew2   = (const float*)d_in[5];
    const float* eb2   = (const float*)d_in[6];
    const float* nw1   = (const float*)d_in[7];
    const float* nb1   = (const float*)d_in[8];
    const float* nw2   = (const float*)d_in[9];
    const float* nb2   = (const float*)d_in[10];
    const float* cw    = (const float*)d_in[11];
    const float* cb    = (const float*)d_in[12];
    const float* gamma = (const float*)d_in[13];
    const float* beta  = (const float*)d_in[14];

    int N = in_sizes[0] / F;
    int E = in_sizes[2] / 2;

    float* xout = (float*)d_out;
    float* pout = (float*)d_out + (size_t)N * F;

    float* XA;   cudaGetSymbolAddress((void**)&XA,   g_XA);
    float* XB;   cudaGetSymbolAddress((void**)&XB,   g_XB);
    float* AGGS; cudaGetSymbolAddress((void**)&AGGS, g_AGGS);
    float* DEG;  cudaGetSymbolAddress((void**)&DEG,  g_DEG);

    int tcb = (N + 127) / 128;

    detect_kernel<<<1, 32>>>(ei, E, N);
    prep_vc<<<1, 128>>>(ew2, cw, eb2, cb);
    zero_kernel<<<2048, 256>>>(N);

    // XA = x @ W1a + eb1 AND XB = x @ W1b — one merged launch
    gemm_rt<0><<<dim3(tcb, 2), 256, SM_RT_TOTAL>>>(
        x, ew1, eb1, XA, ew1 + 128 * F, nullptr, XB, nullptr, nullptr, N);

    // Edge stage
    int eblocks = (E * 32 + 255) / 256;
    edge_kernel<<<eblocks, 256>>>(ei, pos, ew1, E, N);

    // AGG = AGGS @ ew2 + deg*eb2  -> XA
    gemm_rt<0><<<tcb, 256, SM_RT_TOTAL>>>(AGGS, ew2, nullptr, XA,
                                          nullptr, nullptr, nullptr, DEG, eb2, N);
    // H = silu(AGG @ nw1 + nb1)   -> XB
    gemm_rt<1><<<tcb, 256, SM_RT_TOTAL>>>(XA, nw1, nb1, XB,
                                          nullptr, nullptr, nullptr, nullptr, nullptr, N);
    // P = H @ nw2 + nb2           -> AGGS (reuse)
    gemm_rt<0><<<tcb, 256, SM_RT_TOTAL>>>(XB, nw2, nb2, AGGS,
                                          nullptr, nullptr, nullptr, nullptr, nullptr, N);
    // x_out = LN(x + P)
    ln_kernel<<<(N + 7) / 8, 256>>>(AGGS, x, gamma, beta, xout, N);
    // pos_out
    pos_kernel<<<(N * 3 + 255) / 256, 256>>>(pos, pout, N);
}

// round 6
// speedup vs baseline: 1.6267x; 1.0157x over previous
#include <cuda_runtime.h>
#include <cuda_bf16.h>
#include <math.h>
#include <stdint.h>

#define NMAX 50000
#define F 128
#define LN_EPS 1e-5f

// ---------------------------------------------------------------------------
// Scratch (device globals — no allocation allowed)
__device__ float g_XA[NMAX * F];
__device__ float g_XB[NMAX * F];
__device__ float g_AGGS[NMAX * F];
__device__ float g_DELTA[NMAX * 3];
__device__ float g_DEG[NMAX];
__device__ float g_V[F];
__device__ float g_C0;
__device__ int   g_IS64;

// ---------------------------------------------------------------------------
#define FFMA2(acc, a, b) \
    asm("fma.rn.f32x2 %0, %1, %2, %0;" : "+l"(acc) : "l"(a), "l"(b))
__device__ __forceinline__ unsigned long long pack2(float v) {
    unsigned long long r;
    unsigned int u = __float_as_uint(v);
    asm("mov.b64 %0, {%1, %1};" : "=l"(r) : "r"(u));
    return r;
}
__device__ __forceinline__ void unpack2(unsigned long long p, float& lo, float& hi) {
    unsigned int a, b;
    asm("mov.b64 {%0, %1}, %2;" : "=r"(a), "=r"(b) : "l"(p));
    lo = __uint_as_float(a);
    hi = __uint_as_float(b);
}
__device__ __forceinline__ uint32_t smem_u32(const void* p) {
    uint32_t a;
    asm("{ .reg .u64 t; cvta.to.shared.u64 t, %1; cvt.u32.u64 %0, t; }"
        : "=r"(a) : "l"(p));
    return a;
}
#define CP_ASYNC16(dst, src) \
    asm volatile("cp.async.cg.shared.global [%0], [%1], 16;" :: "r"(dst), "l"(src))
#define CP_COMMIT() asm volatile("cp.async.commit_group;" ::: "memory")
#define CP_WAIT0()  asm volatile("cp.async.wait_group 0;" ::: "memory")

// ---------------------------------------------------------------------------
__global__ void detect_kernel(const void* ei, int E, int N) {
    if (blockIdx.x == 0 && threadIdx.x == 0) {
        const long long* p = (const long long*)ei;
        int cnt = (2 * E < 256) ? 2 * E : 256;
        int ok = 1;
        for (int i = 0; i < cnt; i++) {
            long long v = p[i];
            if (v < 0 || v >= N) { ok = 0; break; }
        }
        g_IS64 = ok;
    }
}

__global__ void prep_vc(const float* __restrict__ ew2, const float* __restrict__ cw,
                        const float* __restrict__ eb2, const float* __restrict__ cb) {
    int t = threadIdx.x;
    float s = 0.f;
    for (int o = 0; o < F; o++) s += ew2[t * F + o] * cw[o];
    g_V[t] = s;
    if (t == 0) {
        float c = cb[0];
        for (int o = 0; o < F; o++) c += eb2[o] * cw[o];
        g_C0 = c;
    }
}

__global__ void zero_kernel(int N) {
    int n4 = N * 32;
    float4 z4 = make_float4(0.f, 0.f, 0.f, 0.f);
    float4* a4 = (float4*)g_AGGS;
    int stride = gridDim.x * blockDim.x;
    for (int i = blockIdx.x * blockDim.x + threadIdx.x; i < n4; i += stride) a4[i] = z4;
    for (int i = blockIdx.x * blockDim.x + threadIdx.x; i < N * 3; i += stride) g_DELTA[i] = 0.f;
    for (int i = blockIdx.x * blockDim.x + threadIdx.x; i < N; i += stride) g_DEG[i] = 0.f;
}

// ---------------------------------------------------------------------------
// Pipelined register-tiled GEMM: out[N,128] = A @ W (+bias)(+deg*degvec)(silu)
// 256 threads, 8x8 f32x2 tile per thread. Double-buffered smem, 1 sync/chunk.
// W staged via cp.async (no regs); A prefetched in regs, STS'd post-compute.
// A staging: warp w owns rows (w&3)*32+lane, k-half (w>>2) -> conflict-free STS.
#define AS_STRIDE 132
#define WS_BYTES  16384                  // 32*128*4
#define AS_BYTES  16896                  // 32*132*4
#define SM_AS0    (2 * WS_BYTES)         // 32768
#define SM_RT_TOTAL (2 * WS_BYTES + 2 * AS_BYTES)   // 66560

template <int ACT>
__global__ void __launch_bounds__(256, 2)
gemm_rt(const float* __restrict__ A,
        const float* __restrict__ W0, const float* __restrict__ bias0,
        float* __restrict__ out0,
        const float* __restrict__ W1, const float* __restrict__ bias1,
        float* __restrict__ out1,
        const float* __restrict__ deg, const float* __restrict__ degvec, int N) {
    extern __shared__ char smem[];

    const float* W = W0;
    const float* bias = bias0;
    float* out = out0;
    if (blockIdx.y == 1) { W = W1; bias = bias1; out = out1; }

    int t = threadIdx.x;
    int lane = t & 31, w = t >> 5;
    int txl = lane & 3, tyl = lane >> 2;
    int wx = w & 3, wy = w >> 2;
    int col0 = (wx * 4 + txl) * 8;
    int rowt = (wy * 8 + tyl) * 8;
    int row0 = blockIdx.x * 128;

    uint32_t sb = smem_u32(smem);

    // A staging ownership
    int arl = (w & 3) * 32 + lane;       // local row 0..127
    int kh  = (w >> 2) * 16;             // k-half 0 or 16
    int arow = row0 + arl;
    const float4* Abase = (const float4*)(A + (size_t)arow * F);

    // W staging ownership (cp.async)
    int wk = t >> 3, wcol = (t & 7) * 16;

    unsigned long long acc[8][4];
#pragma unroll
    for (int r = 0; r < 8; r++)
#pragma unroll
        for (int c = 0; c < 4; c++) acc[r][c] = 0ull;

    float4 v[4];

    // --- prologue: stage chunk 0 into buffer 0
    {
        const float* wsrc = W + (size_t)wk * F + wcol;
        uint32_t wdst = sb + (uint32_t)(wk * F + wcol) * 4;
#pragma unroll
        for (int q = 0; q < 4; q++) CP_ASYNC16(wdst + q * 16, wsrc + q * 4);
        CP_COMMIT();
        if (arow < N) {
#pragma unroll
            for (int q = 0; q < 4; q++) v[q] = __ldg(&Abase[(kh >> 2) + q]);
        } else {
#pragma unroll
            for (int q = 0; q < 4; q++) v[q] = make_float4(0.f, 0.f, 0.f, 0.f);
        }
        float* As0 = (float*)(smem + SM_AS0);
#pragma unroll
        for (int q = 0; q < 4; q++) {
            float vals[4] = {v[q].x, v[q].y, v[q].z, v[q].w};
#pragma unroll
            for (int e = 0; e < 4; e++)
                As0[(kh + q * 4 + e) * AS_STRIDE + arl] = vals[e];
        }
        CP_WAIT0();
    }
    __syncthreads();

#pragma unroll 1
    for (int c = 0; c < 4; c++) {
        int cb = c & 1, nb = (c + 1) & 1;
        float* Ws = (float*)(smem + cb * WS_BYTES);
        float* As = (float*)(smem + SM_AS0 + cb * AS_BYTES);

        if (c < 3) {
            // issue staging for chunk c+1 (hidden under compute)
            const float* wsrc = W + (size_t)((c + 1) * 32 + wk) * F + wcol;
            uint32_t wdst = sb + (uint32_t)nb * WS_BYTES + (uint32_t)(wk * F + wcol) * 4;
#pragma unroll
            for (int q = 0; q < 4; q++) CP_ASYNC16(wdst + q * 16, wsrc + q * 4);
            CP_COMMIT();
            if (arow < N) {
                int kb = ((c + 1) * 32 + kh) >> 2;
#pragma unroll
                for (int q = 0; q < 4; q++) v[q] = __ldg(&Abase[kb + q]);
            }
        }

#pragma unroll
        for (int kk = 0; kk < 32; kk++) {
            float4 al = *(const float4*)&As[kk * AS_STRIDE + rowt];
            float4 ah = *(const float4*)&As[kk * AS_STRIDE + rowt + 4];
            unsigned long long a0 = pack2(al.x), a1 = pack2(al.y);
            unsigned long long a2 = pack2(al.z), a3 = pack2(al.w);
            unsigned long long a4 = pack2(ah.x), a5 = pack2(ah.y);
            unsigned long long a6 = pack2(ah.z), a7 = pack2(ah.w);
            ulonglong2 bv0 = *(const ulonglong2*)&Ws[kk * F + col0];
            ulonglong2 bv1 = *(const ulonglong2*)&Ws[kk * F + col0 + 4];
            FFMA2(acc[0][0], a0, bv0.x); FFMA2(acc[0][1], a0, bv0.y);
            FFMA2(acc[0][2], a0, bv1.x); FFMA2(acc[0][3], a0, bv1.y);
            FFMA2(acc[1][0], a1, bv0.x); FFMA2(acc[1][1], a1, bv0.y);
            FFMA2(acc[1][2], a1, bv1.x); FFMA2(acc[1][3], a1, bv1.y);
            FFMA2(acc[2][0], a2, bv0.x); FFMA2(acc[2][1], a2, bv0.y);
            FFMA2(acc[2][2], a2, bv1.x); FFMA2(acc[2][3], a2, bv1.y);
            FFMA2(acc[3][0], a3, bv0.x); FFMA2(acc[3][1], a3, bv0.y);
            FFMA2(acc[3][2], a3, bv1.x); FFMA2(acc[3][3], a3, bv1.y);
            FFMA2(acc[4][0], a4, bv0.x); FFMA2(acc[4][1], a4, bv0.y);
            FFMA2(acc[4][2], a4, bv1.x); FFMA2(acc[4][3], a4, bv1.y);
            FFMA2(acc[5][0], a5, bv0.x); FFMA2(acc[5][1], a5, bv0.y);
            FFMA2(acc[5][2], a5, bv1.x); FFMA2(acc[5][3], a5, bv1.y);
            FFMA2(acc[6][0], a6, bv0.x); FFMA2(acc[6][1], a6, bv0.y);
            FFMA2(acc[6][2], a6, bv1.x); FFMA2(acc[6][3], a6, bv1.y);
            FFMA2(acc[7][0], a7, bv0.x); FFMA2(acc[7][1], a7, bv0.y);
            FFMA2(acc[7][2], a7, bv1.x); FFMA2(acc[7][3], a7, bv1.y);
        }

        if (c < 3) {
            // STS prefetched A into the other buffer (safe: that buffer's last
            // readers finished before the sync that ended iteration c-1)
            float* Asn = (float*)(smem + SM_AS0 + nb * AS_BYTES);
            if (arow >= N) {
#pragma unroll
                for (int q = 0; q < 4; q++) v[q] = make_float4(0.f, 0.f, 0.f, 0.f);
            }
#pragma unroll
            for (int q = 0; q < 4; q++) {
                float vals[4] = {v[q].x, v[q].y, v[q].z, v[q].w};
#pragma unroll
                for (int e = 0; e < 4; e++)
                    Asn[(kh + q * 4 + e) * AS_STRIDE + arl] = vals[e];
            }
            CP_WAIT0();
        }
        __syncthreads();
    }

    // Epilogue
    float bcol[8], dcol[8];
#pragma unroll
    for (int j = 0; j < 8; j++) {
        bcol[j] = bias ? __ldg(&bias[col0 + j]) : 0.f;
        dcol[j] = degvec ? __ldg(&degvec[col0 + j]) : 0.f;
    }
#pragma unroll
    for (int rr = 0; rr < 8; rr++) {
        int row = row0 + rowt + rr;
        if (row < N) {
            float dg = deg ? deg[row] : 0.f;
            float o[8];
#pragma unroll
            for (int cp = 0; cp < 4; cp++) unpack2(acc[rr][cp], o[2 * cp], o[2 * cp + 1]);
#pragma unroll
            for (int j = 0; j < 8; j++) {
                float vv = o[j] + bcol[j] + dg * dcol[j];
                if (ACT == 1) vv = vv / (1.f + __expf(-vv));
                o[j] = vv;
            }
            float4* op = (float4*)(out + (size_t)row * F + col0);
            op[0] = make_float4(o[0], o[1], o[2], o[3]);
            op[1] = make_float4(o[4], o[5], o[6], o[7]);
        }
    }
}

// ---------------------------------------------------------------------------
// Edge kernel: one warp per edge.
__global__ void __launch_bounds__(256)
edge_kernel(const void* __restrict__ ei_raw, const float* __restrict__ pos,
            const float* __restrict__ ew1, int E, int N) {
    int gw = (blockIdx.x * blockDim.x + threadIdx.x) >> 5;
    int lane = threadIdx.x & 31;
    if (gw >= E) return;

    int row, col;
    if (g_IS64) {
        const long long* ei = (const long long*)ei_raw;
        row = (int)ei[gw];
        col = (int)ei[(size_t)E + gw];
    } else {
        const int* ei = (const int*)ei_raw;
        row = ei[gw];
        col = ei[E + gw];
    }

    float dx = pos[row * 3 + 0] - pos[col * 3 + 0];
    float dy = pos[row * 3 + 1] - pos[col * 3 + 1];
    float dz = pos[row * 3 + 2] - pos[col * 3 + 2];
    float dist2 = dx * dx + dy * dy + dz * dz;

    const float4* XA4 = (const float4*)g_XA;
    const float4* XB4 = (const float4*)g_XB;
    float4 a = XA4[(size_t)row * 32 + lane];
    float4 b = XB4[(size_t)col * 32 + lane];
    float4 w = __ldg((const float4*)(ew1 + 256 * F) + lane);

    float p0 = a.x + b.x + dist2 * w.x;
    float p1 = a.y + b.y + dist2 * w.y;
    float p2 = a.z + b.z + dist2 * w.z;
    float p3 = a.w + b.w + dist2 * w.w;

    float s0 = p0 / (1.f + __expf(-p0));
    float s1 = p1 / (1.f + __expf(-p1));
    float s2 = p2 / (1.f + __expf(-p2));
    float s3 = p3 / (1.f + __expf(-p3));

    float* aggp = g_AGGS + (size_t)row * F + lane * 4;
    asm volatile("red.global.add.v4.f32 [%0], {%1, %2, %3, %4};"
                 :: "l"(aggp), "f"(s0), "f"(s1), "f"(s2), "f"(s3) : "memory");

    float4 vv = ((const float4*)g_V)[lane];
    float d = s0 * vv.x + s1 * vv.y + s2 * vv.z + s3 * vv.w;
#pragma unroll
    for (int o = 16; o > 0; o >>= 1) d += __shfl_xor_sync(0xffffffffu, d, o);

    if (lane == 0) {
        float sc = tanhf(d + g_C0);
        atomicAdd(&g_DELTA[row * 3 + 0], sc * dx);
        atomicAdd(&g_DELTA[row * 3 + 1], sc * dy);
        atomicAdd(&g_DELTA[row * 3 + 2], sc * dz);
        atomicAdd(&g_DEG[row], 1.0f);
    }
}

// ---------------------------------------------------------------------------
// Residual + LayerNorm: xout = LN(P + x)
__global__ void __launch_bounds__(256)
ln_kernel(const float* __restrict__ P, const float* __restrict__ x,
          const float* __restrict__ gamma, const float* __restrict__ beta,
          float* __restrict__ xout, int N) {
    int row = blockIdx.x * 8 + (threadIdx.x >> 5);
    int lane = threadIdx.x & 31;
    if (row >= N) return;
    float4 p = ((const float4*)P)[(size_t)row * 32 + lane];
    float4 xv = ((const float4*)x)[(size_t)row * 32 + lane];
    float4 pre = make_float4(p.x + xv.x, p.y + xv.y, p.z + xv.z, p.w + xv.w);
    float s = pre.x + pre.y + pre.z + pre.w;
    float s2 = pre.x * pre.x + pre.y * pre.y + pre.z * pre.z + pre.w * pre.w;
#pragma unroll
    for (int o = 16; o > 0; o >>= 1) {
        s  += __shfl_xor_sync(0xffffffffu, s, o);
        s2 += __shfl_xor_sync(0xffffffffu, s2, o);
    }
    float mean = s * (1.f / F);
    float ri = rsqrtf(s2 * (1.f / F) - mean * mean + LN_EPS);
    float4 g = ((const float4*)gamma)[lane];
    float4 b = ((const float4*)beta)[lane];
    float4 o;
    o.x = g.x * (pre.x - mean) * ri + b.x;
    o.y = g.y * (pre.y - mean) * ri + b.y;
    o.z = g.z * (pre.z - mean) * ri + b.z;
    o.w = g.w * (pre.w - mean) * ri + b.w;
    ((float4*)xout)[(size_t)row * 32 + lane] = o;
}

__global__ void pos_kernel(const float* __restrict__ pos, float* __restrict__ out, int N) {
    int i = blockIdx.x * blockDim.x + threadIdx.x;
    if (i < N * 3) out[i] = pos[i] + g_DELTA[i];
}

// ---------------------------------------------------------------------------
extern "C" void kernel_launch(void* const* d_in, const int* in_sizes, int n_in,
                              void* d_out, int out_size) {
    const float* x     = (const float*)d_in[0];
    const float* pos   = (const float*)d_in[1];
    const void*  ei    = d_in[2];
    const float* ew1   = (const float*)d_in[3];
    const float* eb1   = (const float*)d_in[4];
    const float* ew2   = (const float*)d_in[5];
    const float* eb2   = (const float*)d_in[6];
    const float* nw1   = (const float*)d_in[7];
    const float* nb1   = (const float*)d_in[8];
    const float* nw2   = (const float*)d_in[9];
    const float* nb2   = (const float*)d_in[10];
    const float* cw    = (const float*)d_in[11];
    const float* cb    = (const float*)d_in[12];
    const float* gamma = (const float*)d_in[13];
    const float* beta  = (const float*)d_in[14];

    int N = in_sizes[0] / F;
    int E = in_sizes[2] / 2;

    float* xout = (float*)d_out;
    float* pout = (float*)d_out + (size_t)N * F;

    float* XA;   cudaGetSymbolAddress((void**)&XA,   g_XA);
    float* XB;   cudaGetSymbolAddress((void**)&XB,   g_XB);
    float* AGGS; cudaGetSymbolAddress((void**)&AGGS, g_AGGS);
    float* DEG;  cudaGetSymbolAddress((void**)&DEG,  g_DEG);

    cudaFuncSetAttribute(gemm_rt<0>, cudaFuncAttributeMaxDynamicSharedMemorySize, SM_RT_TOTAL);
    cudaFuncSetAttribute(gemm_rt<1>, cudaFuncAttributeMaxDynamicSharedMemorySize, SM_RT_TOTAL);

    int tcb = (N + 127) / 128;

    detect_kernel<<<1, 32>>>(ei, E, N);
    prep_vc<<<1, 128>>>(ew2, cw, eb2, cb);
    zero_kernel<<<2048, 256>>>(N);

    // XA = x @ W1a + eb1 AND XB = x @ W1b — one merged launch
    gemm_rt<0><<<dim3(tcb, 2), 256, SM_RT_TOTAL>>>(
        x, ew1, eb1, XA, ew1 + 128 * F, nullptr, XB, nullptr, nullptr, N);

    // Edge stage
    int eblocks = (E * 32 + 255) / 256;
    edge_kernel<<<eblocks, 256>>>(ei, pos, ew1, E, N);

    // AGG = AGGS @ ew2 + deg*eb2  -> XA
    gemm_rt<0><<<tcb, 256, SM_RT_TOTAL>>>(AGGS, ew2, nullptr, XA,
                                          nullptr, nullptr, nullptr, DEG, eb2, N);
    // H = silu(AGG @ nw1 + nb1)   -> XB
    gemm_rt<1><<<tcb, 256, SM_RT_TOTAL>>>(XA, nw1, nb1, XB,
                                          nullptr, nullptr, nullptr, nullptr, nullptr, N);
    // P = H @ nw2 + nb2           -> AGGS (reuse)
    gemm_rt<0><<<tcb, 256, SM_RT_TOTAL>>>(XB, nw2, nb2, AGGS,
                                          nullptr, nullptr, nullptr, nullptr, nullptr, N);
    // x_out = LN(x + P)
    ln_kernel<<<(N + 7) / 8, 256>>>(AGGS, x, gamma, beta, xout, N);
    // pos_out
    pos_kernel<<<(N * 3 + 255) / 256, 256>>>(pos, pout, N);
}